// round 11
// baseline (speedup 1.0000x reference)
#include <cuda_runtime.h>
#include <cstdint>

#define B_ 64
#define J_ 25
#define V_ 50000
#define BPB 32          // batches per fk block

#define TM 128          // vertices per CTA tile
#define TN 128          // N cols per CTA tile (= 8 batches * 16)
#define TK 32           // K padded (25 joints -> 32)
#define KS 36           // stage row stride in words (conflict-free frag LDS)
#define SST 76          // S row stride in words (conflict-free epilogue LDS.128)
#define MT ((V_ + TM - 1) / TM)      // 391
#define NT ((B_ * 16) / TN)          // 8

// Device globals (no allocation allowed). Zero-initialized: padded K cols of
// g_Tp (j = 25..31) are never written and stay 0.
__device__ float g_Tp[B_ * 16 * TK];   // tf32-rounded DeltaT, [n][j] n=b*16+r*4+c
__device__ float g_Tbar[B_ * 12];      // fp32 per-batch mean transform rows

__device__ __forceinline__ uint32_t f2tf32(float f) {
    uint32_t u;
    asm("cvt.rna.tf32.f32 %0, %1;" : "=r"(u) : "f"(f));
    return u;
}

// ---------------------------------------------------------------------------
// FK kernel: 2 blocks x 1024 threads, 32 batches/block. Locals in smem; 96
// threads run the sequential chain. Pass 1 computes G, joint_out and per-row
// sums of T; pass 2 recomputes T rows and writes tf32(T - Tbar) into g_Tp.
// ---------------------------------------------------------------------------
__global__ __launch_bounds__(1024)
void fk_kernel(const float* __restrict__ je,
               const float* __restrict__ lp,
               const float* __restrict__ sc,
               const float* __restrict__ gpi,
               const int* __restrict__ parents,
               float* __restrict__ joint_out) {
    __shared__ float ls[BPB * J_ * 12];
    __shared__ float gpis[J_ * 16];
    __shared__ int   par[J_];

    int tid = threadIdx.x;
    int bbase = blockIdx.x * BPB;

    if (tid < J_ * 16) gpis[tid] = gpi[tid];
    if (tid < J_) par[tid] = parents[tid];

    for (int idx = tid; idx < BPB * J_; idx += blockDim.x) {
        int j = idx % J_;
        int gidx = bbase * J_ + idx;
        float ex = je[gidx*3+0], ey = je[gidx*3+1], ez = je[gidx*3+2];
        float sx, cx, sy, cy, sz, cz;
        sincosf(ex, &sx, &cx);
        sincosf(ey, &sy, &cy);
        sincosf(ez, &sz, &cz);
        float R00 = cz*cy, R01 = cz*sy*sx - sz*cx, R02 = cz*sy*cx + sz*sx;
        float R10 = sz*cy, R11 = sz*sy*sx + cz*cx, R12 = sz*sy*cx - cz*sx;
        float R20 = -sy,   R21 = cy*sx,            R22 = cy*cx;
        const float* L0 = lp + j*16;
        float* out = ls + idx*12;
        #pragma unroll
        for (int r = 0; r < 3; ++r) {
            float a0 = L0[r*4+0], a1 = L0[r*4+1], a2 = L0[r*4+2];
            out[r*4+0] = a0*R00 + a1*R10 + a2*R20;
            out[r*4+1] = a0*R01 + a1*R11 + a2*R21;
            out[r*4+2] = a0*R02 + a1*R12 + a2*R22;
            out[r*4+3] = L0[r*4+3] + sc[j*3+r];
        }
    }

    __syncthreads();

    if (tid >= BPB * 3) return;
    int bl = tid / 3, r = tid % 3;
    int b = bbase + bl;

    float Grow[J_][4];
    float pr0 = 0.f, pr1 = 0.f, pr2 = 0.f, pr3 = 0.f;
    int prevj = -2;
    float s0 = 0.f, s1 = 0.f, s2 = 0.f, s3 = 0.f;   // sums of T rows over j

    for (int j = 0; j < J_; ++j) {
        int pj = par[j];
        float g0, g1, g2, g3;
        if (pj < 0) {
            g0 = (r == 0) ? 1.f : 0.f;
            g1 = (r == 1) ? 1.f : 0.f;
            g2 = (r == 2) ? 1.f : 0.f;
            g3 = 0.f;
        } else {
            float p0, p1, p2, p3;
            if (pj == prevj) { p0 = pr0; p1 = pr1; p2 = pr2; p3 = pr3; }
            else { p0 = Grow[pj][0]; p1 = Grow[pj][1]; p2 = Grow[pj][2]; p3 = Grow[pj][3]; }
            const float* L = ls + (bl*J_ + j) * 12;
            g0 = p0*L[0] + p1*L[4] + p2*L[8];
            g1 = p0*L[1] + p1*L[5] + p2*L[9];
            g2 = p0*L[2] + p1*L[6] + p2*L[10];
            g3 = p0*L[3] + p1*L[7] + p2*L[11] + p3;
        }
        Grow[j][0] = g0; Grow[j][1] = g1; Grow[j][2] = g2; Grow[j][3] = g3;
        pr0 = g0; pr1 = g1; pr2 = g2; pr3 = g3; prevj = j;

        const float* P = gpis + j*16;
        s0 += g0*P[0] + g1*P[4] + g2*P[8];
        s1 += g0*P[1] + g1*P[5] + g2*P[9];
        s2 += g0*P[2] + g1*P[6] + g2*P[10];
        s3 += g0*P[3] + g1*P[7] + g2*P[11] + g3;
        joint_out[(b*J_ + j)*3 + r] = g3;
    }

    const float inv = 1.0f / (float)J_;
    float m0 = s0*inv, m1 = s1*inv, m2 = s2*inv, m3 = s3*inv;
    g_Tbar[b*12 + r*4 + 0] = m0;
    g_Tbar[b*12 + r*4 + 1] = m1;
    g_Tbar[b*12 + r*4 + 2] = m2;
    g_Tbar[b*12 + r*4 + 3] = m3;

    // Pass 2: DeltaT = T - Tbar, tf32-rounded, scattered K-major
    int nbase = (b * 16 + r * 4);
    for (int j = 0; j < J_; ++j) {
        float g0 = Grow[j][0], g1 = Grow[j][1], g2 = Grow[j][2], g3 = Grow[j][3];
        const float* P = gpis + j*16;
        float t0 = g0*P[0] + g1*P[4] + g2*P[8]          - m0;
        float t1 = g0*P[1] + g1*P[5] + g2*P[9]          - m1;
        float t2 = g0*P[2] + g1*P[6] + g2*P[10]         - m2;
        float t3 = g0*P[3] + g1*P[7] + g2*P[11] + g3    - m3;
        g_Tp[(nbase + 0) * TK + j] = __uint_as_float(f2tf32(t0));
        g_Tp[(nbase + 1) * TK + j] = __uint_as_float(f2tf32(t1));
        g_Tp[(nbase + 2) * TK + j] = __uint_as_float(f2tf32(t2));
        g_Tp[(nbase + 3) * TK + j] = __uint_as_float(f2tf32(t3));
    }
}

// ---------------------------------------------------------------------------
// mma.sync m16n8k8 tf32 (baseline PTX, sm_80+; assembles for sm_100)
// ---------------------------------------------------------------------------
__device__ __forceinline__ void mma_tf32(float* d, const uint32_t* a,
                                         const uint32_t* b) {
    asm volatile(
        "mma.sync.aligned.m16n8k8.row.col.f32.tf32.tf32.f32 "
        "{%0,%1,%2,%3}, {%4,%5,%6,%7}, {%8,%9}, {%0,%1,%2,%3};"
        : "+f"(d[0]), "+f"(d[1]), "+f"(d[2]), "+f"(d[3])
        : "r"(a[0]), "r"(a[1]), "r"(a[2]), "r"(a[3]), "r"(b[0]), "r"(b[1]));
}

// ---------------------------------------------------------------------------
// Skinning via warp-level tf32 GEMM + fused epilogue.
// CTA: 256 thr (8 warps), tile 128 vtx x 128 N (8 batches). Warp tile m64n32.
// S = W_tf32 . DeltaTp_tf32 (K=32); M = Tbar + S re-added in fp32 (valid since
// sum_j w = 1). Epilogue routes S through smem (union with stage buffers).
// ---------------------------------------------------------------------------
__global__ __launch_bounds__(256, 2)
void skin_mma_kernel(const float* __restrict__ vtx,
                     const float* __restrict__ W,
                     const float* __restrict__ pc,
                     const float* __restrict__ ic,
                     float* __restrict__ mesh_out) {
    // union: stage (ws 128x36 + tps 128x36 = 36864B)  vs  S (128x76 = 38912B)
    __shared__ __align__(16) unsigned char usm[TM * SST * 4];
    __shared__ float tbars[8 * 16];
    __shared__ float vts[TM * 3];

    float* ws  = reinterpret_cast<float*>(usm);
    float* tps = reinterpret_cast<float*>(usm) + TM * KS;
    float* S   = reinterpret_cast<float*>(usm);

    int tid = threadIdx.x;
    int wid = tid >> 5, lane = tid & 31;
    int gid = lane >> 2, tig = lane & 3;
    int v0 = blockIdx.x * TM;
    int bbase = blockIdx.y * 8;
    int nv = min(TM, V_ - v0);

    // ---- stage ----
    float4 z4 = make_float4(0.f, 0.f, 0.f, 0.f);
    float4* stp = reinterpret_cast<float4*>(usm);
    for (int i = tid; i < 2 * TM * KS / 4; i += 256) stp[i] = z4;
    if (tid < 96) tbars[(tid / 12) * 16 + (tid % 12)] = g_Tbar[bbase * 12 + tid];
    for (int i = tid; i < nv * 3; i += 256) vts[i] = vtx[v0 * 3 + i];
    __syncthreads();

    for (int i = tid; i < nv * J_; i += 256) {
        int r = i / J_, c = i - r * J_;
        ws[r * KS + c] = __uint_as_float(f2tf32(W[(size_t)v0 * J_ + i]));
    }
    const float* tsrc = g_Tp + bbase * 16 * TK;
    for (int i = tid; i < TN * TK; i += 256) {
        int n = i >> 5, j = i & 31;
        tps[n * KS + j] = tsrc[i];
    }
    __syncthreads();

    // ---- GEMM: warp tile m64n32 ----
    int wm = (wid & 1) * 64;
    int wn = (wid >> 1) * 32;

    float acc[4][4][4];
    #pragma unroll
    for (int mi = 0; mi < 4; ++mi)
        #pragma unroll
        for (int ni = 0; ni < 4; ++ni)
            #pragma unroll
            for (int k = 0; k < 4; ++k) acc[mi][ni][k] = 0.f;

    #pragma unroll
    for (int ks = 0; ks < 4; ++ks) {
        int k0 = ks * 8;
        uint32_t A[4][4], Bf[4][2];
        #pragma unroll
        for (int mi = 0; mi < 4; ++mi) {
            const float* p = ws + (wm + mi * 16 + gid) * KS + k0 + tig;
            A[mi][0] = __float_as_uint(p[0]);
            A[mi][1] = __float_as_uint(p[8 * KS]);
            A[mi][2] = __float_as_uint(p[4]);
            A[mi][3] = __float_as_uint(p[8 * KS + 4]);
        }
        #pragma unroll
        for (int ni = 0; ni < 4; ++ni) {
            const float* p = tps + (wn + ni * 8 + gid) * KS + k0 + tig;
            Bf[ni][0] = __float_as_uint(p[0]);
            Bf[ni][1] = __float_as_uint(p[4]);
        }
        #pragma unroll
        for (int mi = 0; mi < 4; ++mi)
            #pragma unroll
            for (int ni = 0; ni < 4; ++ni)
                mma_tf32(acc[mi][ni], A[mi], Bf[ni]);
    }
    __syncthreads();   // stage buffers now dead; reuse as S

    // ---- epilogue in two 64-col halves (4 batches each) ----
    #pragma unroll
    for (int h = 0; h < 2; ++h) {
        if (((wid >> 1) >> 1) == h) {          // warps owning cols [64h, 64h+64)
            int scol = wn - h * 64;
            #pragma unroll
            for (int mi = 0; mi < 4; ++mi) {
                int row = wm + mi * 16 + gid;
                #pragma unroll
                for (int ni = 0; ni < 4; ++ni) {
                    int col = scol + ni * 8 + 2 * tig;
                    *reinterpret_cast<float2*>(&S[row * SST + col]) =
                        make_float2(acc[mi][ni][0], acc[mi][ni][1]);
                    *reinterpret_cast<float2*>(&S[(row + 8) * SST + col]) =
                        make_float2(acc[mi][ni][2], acc[mi][ni][3]);
                }
            }
        }
        __syncthreads();

        #pragma unroll
        for (int it8 = 0; it8 < 2; ++it8) {
            int it = tid + it8 * 256;
            int vl = it & (TM - 1), blc = it >> 7;   // 0..3
            int v = v0 + vl;
            if (v < V_) {
                int b = bbase + h * 4 + blc;
                const float4* Sr = reinterpret_cast<const float4*>(&S[vl * SST + blc * 16]);
                float4 m0 = Sr[0], m1 = Sr[1], m2 = Sr[2];
                const float4* Tb = reinterpret_cast<const float4*>(&tbars[(h * 4 + blc) * 16]);
                float4 t0 = Tb[0], t1 = Tb[1], t2 = Tb[2];
                int o = (b * V_ + v) * 3;
                float px = vts[vl*3+0] + pc[o+0] + ic[o+0];
                float py = vts[vl*3+1] + pc[o+1] + ic[o+1];
                float pz = vts[vl*3+2] + pc[o+2] + ic[o+2];
                mesh_out[o+0] = fmaf(m0.x+t0.x, px, fmaf(m0.y+t0.y, py,
                                fmaf(m0.z+t0.z, pz, m0.w+t0.w)));
                mesh_out[o+1] = fmaf(m1.x+t1.x, px, fmaf(m1.y+t1.y, py,
                                fmaf(m1.z+t1.z, pz, m1.w+t1.w)));
                mesh_out[o+2] = fmaf(m2.x+t2.x, px, fmaf(m2.y+t2.y, py,
                                fmaf(m2.z+t2.z, pz, m2.w+t2.w)));
            }
        }
        __syncthreads();
    }
}

// ---------------------------------------------------------------------------
extern "C" void kernel_launch(void* const* d_in, const int* in_sizes, int n_in,
                              void* d_out, int out_size) {
    const float* joint_euler = (const float*)d_in[0];
    const float* vtx         = (const float*)d_in[1];
    const float* W           = (const float*)d_in[2];
    const float* local_pose  = (const float*)d_in[3];
    const float* gpi         = (const float*)d_in[4];
    const float* sc          = (const float*)d_in[5];
    const float* pc          = (const float*)d_in[6];
    const float* ic          = (const float*)d_in[7];
    const int*   parents     = (const int*)d_in[8];
    float* out = (float*)d_out;

    fk_kernel<<<B_ / BPB, 1024>>>(joint_euler, local_pose, sc, gpi, parents, out);
    dim3 grid(MT, NT);
    skin_mma_kernel<<<grid, 256>>>(vtx, W, pc, ic, out + B_*J_*3);
}